// round 10
// baseline (speedup 1.0000x reference)
#include <cuda_runtime.h>
#include <math.h>

// 9x9 max-dilation, SAME padding (-inf border). Horizontal-first + van Herk
// vertical streaming; each raw row loaded once, no smem, no barriers.
//   - CTA = 256 thr (8 warps), full 1024-col width, 32 output rows
//   - per raw row: LDG.128 (4 cols/lane) + predicated edge-lane halo LDG,
//     horizontal 9-max via prefix/suffix + 8 shuffles
//   - vertical 9-max: van Herk — suffix array S[8] (in-place refresh) +
//     running prefix, emits one output row per streamed input row
//   - strips 1..30 take a fully unguarded fast path
// Input 16x1024x1024x1 fp32.

#define IMG 1024
#define NTH 256
#define TH 32             // output rows per CTA
#define NITER (TH / 8)    // 4

__device__ __forceinline__ float4 max4(float4 a, float4 b) {
    return make_float4(fmaxf(a.x, b.x), fmaxf(a.y, b.y),
                       fmaxf(a.z, b.z), fmaxf(a.w, b.w));
}

#define NEGF4 make_float4(-INFINITY, -INFINITY, -INFINITY, -INFINITY)

// horizontal 9-max of one row: v = own 4 cols, hv = 4-col halo (valid only
// on lanes 0 / 31). Windows: out col gx+k spans [gx+k-4, gx+k+4].
__device__ __forceinline__ float4 horiz9(float4 v, float4 hv, int lane) {
    const float p0 = v.x;
    const float p1 = fmaxf(p0, v.y);
    const float p2 = fmaxf(p1, v.z);
    const float p3 = fmaxf(p2, v.w);
    const float s3 = v.w;
    const float s2 = fmaxf(v.z, s3);
    const float s1 = fmaxf(v.y, s2);
    const float s0 = p3;

    float sU0 = __shfl_up_sync(0xffffffffu, s0, 1);
    float sU1 = __shfl_up_sync(0xffffffffu, s1, 1);
    float sU2 = __shfl_up_sync(0xffffffffu, s2, 1);
    float sU3 = __shfl_up_sync(0xffffffffu, s3, 1);
    float pD0 = __shfl_down_sync(0xffffffffu, p0, 1);
    float pD1 = __shfl_down_sync(0xffffffffu, p1, 1);
    float pD2 = __shfl_down_sync(0xffffffffu, p2, 1);
    float pD3 = __shfl_down_sync(0xffffffffu, p3, 1);

    if (lane == 0) {   // left halo = cols gx-4..gx-1
        sU3 = hv.w;
        sU2 = fmaxf(hv.z, sU3);
        sU1 = fmaxf(hv.y, sU2);
        sU0 = fmaxf(hv.x, sU1);
    }
    if (lane == 31) {  // right halo = cols gx+4..gx+7
        pD0 = hv.x;
        pD1 = fmaxf(pD0, hv.y);
        pD2 = fmaxf(pD1, hv.z);
        pD3 = fmaxf(pD2, hv.w);
    }

    float4 o;
    o.x = fmaxf(fmaxf(sU0, s0), pD0);
    o.y = fmaxf(fmaxf(sU1, s0), pD1);
    o.z = fmaxf(fmaxf(sU2, s0), pD2);
    o.w = fmaxf(fmaxf(sU3, s0), pD3);
    return o;
}

template<bool GUARD>
__device__ __forceinline__ float4 ldhm(const float* __restrict__ img,
                                       int gy, int gx, int hx, bool hok, int lane) {
    // load own row segment + edge halo, return horizontal 9-max
    float4 v, hv;
    if (GUARD && (unsigned)gy >= (unsigned)IMG) {
        v = NEGF4; hv = NEGF4;
    } else {
        v = *(const float4*)(img + (size_t)gy * IMG + gx);
        hv = hok ? *(const float4*)(img + (size_t)gy * IMG + hx) : NEGF4;
    }
    return horiz9(v, hv, lane);
}

template<bool GUARD>
__device__ __forceinline__ void process_strip(
    const float* __restrict__ img, float* __restrict__ oimg,
    int y0, int lane, int w)
{
    const int gx = w * 128 + lane * 4;     // own 4 cols
    const bool edge = (lane == 0) || (lane == 31);
    const int hx = (lane == 31) ? gx + 4 : gx - 4;   // halo 4 cols
    const bool hok = edge && ((unsigned)hx <= (unsigned)(IMG - 4));

    // ---- prologue: raw rows y0-4 .. y0+3 -> hm -> suffix array S ----
    float4 S[8];
    #pragma unroll
    for (int j = 0; j < 8; j++)
        S[j] = ldhm<GUARD>(img, y0 - 4 + j, gx, hx, hok, lane);
    #pragma unroll
    for (int j = 6; j >= 0; j--) S[j] = max4(S[j], S[j + 1]);

    // ---- stream: 4 iterations x 8 rows; 1 output row per input row ----
    #pragma unroll
    for (int k = 0; k < NITER; k++) {
        float4 P = NEGF4;
        #pragma unroll
        for (int t = 0; t < 8; t++) {
            const int gy = y0 + 4 + 8 * k + t;       // new raw row
            const float4 hm = ldhm<GUARD>(img, gy, gx, hx, hok, lane);
            P = max4(P, hm);
            const float4 o = max4(S[t], P);          // out row y0+8k+t
            *(float4*)(oimg + (size_t)(y0 + 8 * k + t) * IMG + gx) = o;
            S[t] = hm;                               // refresh suffix source
        }
        // backward suffix scan for next iteration
        #pragma unroll
        for (int j = 6; j >= 0; j--) S[j] = max4(S[j], S[j + 1]);
    }
}

__global__ __launch_bounds__(NTH, 4)
void dilate9_kernel(const float* __restrict__ in, float* __restrict__ out) {
    const int strip = blockIdx.x;     // 0..31 (32-row strips)
    const int bz    = blockIdx.y;     // batch
    const int tid   = threadIdx.x;
    const int lane  = tid & 31;
    const int w     = tid >> 5;

    const float* img = in  + (size_t)bz * IMG * IMG;
    float*      oimg = out + (size_t)bz * IMG * IMG;

    const int y0 = strip * TH;
    // interior strips: raw rows [y0-4, y0+35] within [0,1024)
    if (strip >= 1 && strip <= (IMG / TH) - 2)
        process_strip<false>(img, oimg, y0, lane, w);
    else
        process_strip<true>(img, oimg, y0, lane, w);
}

extern "C" void kernel_launch(void* const* d_in, const int* in_sizes, int n_in,
                              void* d_out, int out_size) {
    const float* in = (const float*)d_in[0];
    float* out = (float*)d_out;
    const int batch = in_sizes[0] / (IMG * IMG);
    dim3 grid(IMG / TH, batch);
    dilate9_kernel<<<grid, NTH>>>(in, out);
}

// round 12
// speedup vs baseline: 1.2614x; 1.2614x over previous
#include <cuda_runtime.h>
#include <math.h>
#include <stdint.h>

// 9x9 max-dilation, SAME padding. cp.async (LDGSTS) bulk-staged tiles:
//   - CTA = 256 thr, tile = 256 out cols x 32 out rows; raw 264x40 fp32 in
//     static smem (42.24KB -> no cudaFuncSetAttribute, ~5 CTA/SM)
//   - loads: cp.async.cg 16B fire-and-forget (2640 ops/CTA, one commit
//     group); border handling via src-size=0 zero fill (input >= 0, so 0
//     acts as -inf for the max)
//   - compute: horizontal 9-max from smem (3x LDS.128 + 17 FMNMX per 4 px,
//     halo resident in smem -> no shuffles, no guards), vertical van Herk
//     (suffix S[8] + running prefix) -> 8 out rows per thread
//   - load/compute overlap comes from ~5 resident CTAs per SM
// Input 16x1024x1024x1 fp32.

#define IMG 1024
#define TILE_W 256
#define TILE_H 32
#define RAW_H 40
#define PITCH 264          // floats per smem row
#define QPR 66             // float4 per raw row
#define NTH 256

__device__ __forceinline__ float4 max4(float4 a, float4 b) {
    return make_float4(fmaxf(a.x, b.x), fmaxf(a.y, b.y),
                       fmaxf(a.z, b.z), fmaxf(a.w, b.w));
}

__device__ __forceinline__ void cp16(uint32_t dst, const float* src, bool valid) {
    int sz = valid ? 16 : 0;
    asm volatile("cp.async.cg.shared.global [%0], [%1], 16, %2;\n"
                 :: "r"(dst), "l"(src), "r"(sz));
}

// horizontal 9-max of 4 outputs from 12 smem floats at row r, col c0
__device__ __forceinline__ float4 hmax_row(const float* sm, int r, int c0) {
    const float* rp = sm + r * PITCH + c0;
    const float4 a = *(const float4*)rp;
    const float4 b = *(const float4*)(rp + 4);
    const float4 c = *(const float4*)(rp + 8);
    const float q  = fmaxf(fmaxf(b.x, b.y), fmaxf(b.z, b.w));  // v4..v7
    const float s3 = a.w;
    const float s2 = fmaxf(a.z, s3);
    const float s1 = fmaxf(a.y, s2);
    const float s0 = fmaxf(a.x, s1);
    const float p8 = c.x;
    const float p9  = fmaxf(p8, c.y);
    const float p10 = fmaxf(p9, c.z);
    const float p11 = fmaxf(p10, c.w);
    float4 o;
    o.x = fmaxf(fmaxf(s0, q), p8);
    o.y = fmaxf(fmaxf(s1, q), p9);
    o.z = fmaxf(fmaxf(s2, q), p10);
    o.w = fmaxf(fmaxf(s3, q), p11);
    return o;
}

__global__ __launch_bounds__(NTH)
void dilate9_kernel(const float* __restrict__ in, float* __restrict__ out) {
    __shared__ __align__(16) float sm[RAW_H * PITCH];   // 42240 B

    const int bx = blockIdx.x;        // x tile (0..3)
    const int by = blockIdx.y;        // y tile (0..31)
    const int bz = blockIdx.z;        // batch
    const int tid = threadIdx.x;

    const float* img = in  + (size_t)bz * IMG * IMG;
    float*      oimg = out + (size_t)bz * IMG * IMG;

    const int x0 = bx * TILE_W;
    const int y0 = by * TILE_H;

    const uint32_t sbase = (uint32_t)__cvta_generic_to_shared(sm);

    // ---- stage raw tile: rows y0-4 .. y0+35, cols x0-4 .. x0+259 ----
    #pragma unroll 4
    for (int i = tid; i < RAW_H * QPR; i += NTH) {
        const int row = i / QPR;
        const int q   = i - row * QPR;
        const int gy = y0 - 4 + row;
        const int gx = x0 - 4 + q * 4;
        const bool v = ((unsigned)gy < (unsigned)IMG) &&
                       ((unsigned)gx <= (unsigned)(IMG - 4));
        const float* src = img + (v ? ((size_t)gy * IMG + gx) : 0);
        cp16(sbase + (uint32_t)(row * QPR + q) * 16u, src, v);
    }
    asm volatile("cp.async.commit_group;\n" ::: "memory");
    asm volatile("cp.async.wait_group 0;\n" ::: "memory");
    __syncthreads();

    // ---- compute: 64 col groups x 4 row streams ----
    const int g  = tid & 63;          // col group: 4 cols
    const int rs = tid >> 6;          // row stream 0..3
    const int c0 = g * 4;             // smem col of first window element
    const int r0 = rs * 8;            // first raw row of stream

    // suffix maxes over hm rows r0..r0+7
    float4 S[8];
    #pragma unroll
    for (int j = 0; j < 8; j++) S[j] = hmax_row(sm, r0 + j, c0);
    #pragma unroll
    for (int j = 6; j >= 0; j--) S[j] = max4(S[j], S[j + 1]);

    // stream prefix over hm rows r0+8..r0+15, emit 8 out rows
    float4 P;
    const int oy0 = y0 + rs * 8;
    #pragma unroll
    for (int t = 0; t < 8; t++) {
        const float4 hm = hmax_row(sm, r0 + 8 + t, c0);
        P = (t == 0) ? hm : max4(P, hm);
        const float4 o = max4(S[t], P);
        *(float4*)(oimg + (size_t)(oy0 + t) * IMG + x0 + c0) = o;
    }
}

extern "C" void kernel_launch(void* const* d_in, const int* in_sizes, int n_in,
                              void* d_out, int out_size) {
    const float* in = (const float*)d_in[0];
    float* out = (float*)d_out;
    const int batch = in_sizes[0] / (IMG * IMG);
    dim3 grid(IMG / TILE_W, IMG / TILE_H, batch);
    dilate9_kernel<<<grid, NTH>>>(in, out);
}

// round 13
// speedup vs baseline: 1.2922x; 1.0244x over previous
#include <cuda_runtime.h>
#include <math.h>
#include <stdint.h>

// 9x9 max-dilation, SAME padding. cp.async-staged 256x64 tiles, two chained
// van Herk chunks per thread:
//   - CTA = 256 thr; tile = 256 out cols x 64 out rows; raw 264x72 fp32 in
//     dynamic smem (76KB, 2 CTA/SM); read amp 1.125
//   - loads: cp.async.cg 16B fire-and-forget; borders via src-size=0 zero
//     fill (input >= 0 so 0 is the max identity)
//   - compute: 64 col-groups (4 cols) x 4 row-streams (16 out rows).
//     horizontal 9-max from smem (3x LDS.128, halo resident -> no shuffles,
//     no guards); vertical = two van Herk chunks of 8, middle hmax rows kept
//     in registers (1.5 hmax evals per output row instead of 2.0)
// Input 16x1024x1024x1 fp32.

#define IMG 1024
#define TILE_W 256
#define TILE_H 64
#define RAW_H 72
#define PITCH 264          // floats per smem row
#define QPR 66             // float4 per raw row
#define NTH 256
#define SMEM_BYTES (RAW_H * PITCH * 4)   // 76032

__device__ __forceinline__ float4 max4(float4 a, float4 b) {
    return make_float4(fmaxf(a.x, b.x), fmaxf(a.y, b.y),
                       fmaxf(a.z, b.z), fmaxf(a.w, b.w));
}

__device__ __forceinline__ void cp16(uint32_t dst, const float* src, bool valid) {
    int sz = valid ? 16 : 0;
    asm volatile("cp.async.cg.shared.global [%0], [%1], 16, %2;\n"
                 :: "r"(dst), "l"(src), "r"(sz));
}

// horizontal 9-max of 4 outputs from 12 smem floats at row r, col c0
__device__ __forceinline__ float4 hmax_row(const float* sm, int r, int c0) {
    const float* rp = sm + r * PITCH + c0;
    const float4 a = *(const float4*)rp;
    const float4 b = *(const float4*)(rp + 4);
    const float4 c = *(const float4*)(rp + 8);
    const float q  = fmaxf(fmaxf(b.x, b.y), fmaxf(b.z, b.w));  // v4..v7
    const float s3 = a.w;
    const float s2 = fmaxf(a.z, s3);
    const float s1 = fmaxf(a.y, s2);
    const float s0 = fmaxf(a.x, s1);
    const float p8 = c.x;
    const float p9  = fmaxf(p8, c.y);
    const float p10 = fmaxf(p9, c.z);
    const float p11 = fmaxf(p10, c.w);
    float4 o;
    o.x = fmaxf(fmaxf(s0, q), p8);
    o.y = fmaxf(fmaxf(s1, q), p9);
    o.z = fmaxf(fmaxf(s2, q), p10);
    o.w = fmaxf(fmaxf(s3, q), p11);
    return o;
}

__global__ __launch_bounds__(NTH)
void dilate9_kernel(const float* __restrict__ in, float* __restrict__ out) {
    extern __shared__ __align__(16) float sm[];   // RAW_H x PITCH

    const int bx = blockIdx.x;        // x tile (0..3)
    const int by = blockIdx.y;        // y tile (0..15)
    const int bz = blockIdx.z;        // batch
    const int tid = threadIdx.x;

    const float* img = in  + (size_t)bz * IMG * IMG;
    float*      oimg = out + (size_t)bz * IMG * IMG;

    const int x0 = bx * TILE_W;
    const int y0 = by * TILE_H;

    const uint32_t sbase = (uint32_t)__cvta_generic_to_shared(sm);

    // ---- stage raw tile: rows y0-4 .. y0+67, cols x0-4 .. x0+259 ----
    #pragma unroll 4
    for (int i = tid; i < RAW_H * QPR; i += NTH) {
        const int row = i / QPR;
        const int q   = i - row * QPR;
        const int gy = y0 - 4 + row;
        const int gx = x0 - 4 + q * 4;
        const bool v = ((unsigned)gy < (unsigned)IMG) &&
                       ((unsigned)gx <= (unsigned)(IMG - 4));
        const float* src = img + (v ? ((size_t)gy * IMG + gx) : 0);
        cp16(sbase + (uint32_t)(row * QPR + q) * 16u, src, v);
    }
    asm volatile("cp.async.commit_group;\n" ::: "memory");
    asm volatile("cp.async.wait_group 0;\n" ::: "memory");
    __syncthreads();

    // ---- compute: 64 col groups x 4 row streams of 16 out rows ----
    const int g  = tid & 63;          // col group: 4 cols (16B stride, no conflicts)
    const int rs = tid >> 6;          // row stream 0..3
    const int c0 = g * 4;             // smem col of first window element
    const int r0 = rs * 16;           // first raw row of stream

    // chunk 1: suffix over hm rows r0..r0+7
    float4 S[8];
    #pragma unroll
    for (int j = 0; j < 8; j++) S[j] = hmax_row(sm, r0 + j, c0);
    #pragma unroll
    for (int j = 6; j >= 0; j--) S[j] = max4(S[j], S[j + 1]);

    // chunk 1 stream: hm rows r0+8..r0+15 (saved in H), emit out rows 0..7
    float4 H[8];
    float4 P;
    const int oy0 = y0 + rs * 16;
    #pragma unroll
    for (int t = 0; t < 8; t++) {
        H[t] = hmax_row(sm, r0 + 8 + t, c0);
        P = (t == 0) ? H[t] : max4(P, H[t]);
        const float4 o = max4(S[t], P);
        *(float4*)(oimg + (size_t)(oy0 + t) * IMG + x0 + c0) = o;
    }

    // chunk 2: suffix of H in place (H[t] = max of original H[t..7])
    #pragma unroll
    for (int j = 6; j >= 0; j--) H[j] = max4(H[j], H[j + 1]);

    // chunk 2 stream: hm rows r0+16..r0+23, emit out rows 8..15
    #pragma unroll
    for (int t = 0; t < 8; t++) {
        const float4 hm = hmax_row(sm, r0 + 16 + t, c0);
        P = (t == 0) ? hm : max4(P, hm);
        const float4 o = max4(H[t], P);
        *(float4*)(oimg + (size_t)(oy0 + 8 + t) * IMG + x0 + c0) = o;
    }
}

extern "C" void kernel_launch(void* const* d_in, const int* in_sizes, int n_in,
                              void* d_out, int out_size) {
    const float* in = (const float*)d_in[0];
    float* out = (float*)d_out;
    const int batch = in_sizes[0] / (IMG * IMG);

    cudaFuncSetAttribute(dilate9_kernel,
                         cudaFuncAttributeMaxDynamicSharedMemorySize, SMEM_BYTES);

    dim3 grid(IMG / TILE_W, IMG / TILE_H, batch);
    dilate9_kernel<<<grid, NTH, SMEM_BYTES>>>(in, out);
}

// round 15
// speedup vs baseline: 1.3571x; 1.0502x over previous
#include <cuda_runtime.h>
#include <math.h>
#include <stdint.h>

// 9x9 max-dilation, SAME padding. cp.async-staged 256x64 tiles with
// intra-CTA load/compute pipelining via mbarrier completion tracking:
//   - CTA = 256 thr; tile = 256 out cols x 64 out rows; raw 264x72 fp32 in
//     dynamic smem (76KB, 2 CTA/SM); read amp 1.125
//   - group 0 = raw rows 0..39 -> mbar0; group 1 = rows 40..71 -> mbar1
//     cp.async.mbarrier.arrive.NOINC: expected count stays at init (256);
//     each thread's arrive fires when all its prior cp.asyncs complete,
//     so mbar1 also covers group 0.
//   - warps with row-streams 0..1 (tid<128) wait mbar0 only and compute
//     while group 1 is still loading; tid>=128 wait mbar1
//   - borders via cp.async src-size=0 zero fill (input >= 0 -> 0 is the
//     max identity)
//   - compute: horizontal 9-max from smem (3x LDS.128, halo resident),
//     vertical = two chained van Herk chunks (16 out rows/thread, 1.5
//     hmax evals per output row)
// Input 16x1024x1024x1 fp32.

#define IMG 1024
#define TILE_W 256
#define TILE_H 64
#define RAW_H 72
#define PITCH 264          // floats per smem row
#define QPR 66             // float4 per raw row
#define NTH 256
#define G0_ROWS 40         // group 0: raw rows 0..39
#define SMEM_BYTES (RAW_H * PITCH * 4)   // 76032

__device__ __forceinline__ float4 max4(float4 a, float4 b) {
    return make_float4(fmaxf(a.x, b.x), fmaxf(a.y, b.y),
                       fmaxf(a.z, b.z), fmaxf(a.w, b.w));
}

__device__ __forceinline__ void cp16(uint32_t dst, const float* src, bool valid) {
    int sz = valid ? 16 : 0;
    asm volatile("cp.async.cg.shared.global [%0], [%1], 16, %2;\n"
                 :: "r"(dst), "l"(src), "r"(sz));
}

__device__ __forceinline__ void mbar_init(uint32_t a, uint32_t cnt) {
    asm volatile("mbarrier.init.shared.b64 [%0], %1;" :: "r"(a), "r"(cnt) : "memory");
}
// .noinc: do NOT bump expected count; arrive fires when this thread's prior
// cp.asyncs complete. (Plain .arrive increments expected count -> deadlock.)
__device__ __forceinline__ void cp_arrive_noinc(uint32_t a) {
    asm volatile("cp.async.mbarrier.arrive.noinc.shared.b64 [%0];" :: "r"(a) : "memory");
}
__device__ __forceinline__ void mbar_wait(uint32_t a) {
    asm volatile(
        "{\n\t.reg .pred P;\n"
        "WL_%=:\n\t"
        "mbarrier.try_wait.parity.shared.b64 P, [%0], 0, 0x989680;\n\t"
        "@P bra WD_%=;\n\t"
        "bra WL_%=;\n"
        "WD_%=:\n\t}"
        :: "r"(a) : "memory");
}

// horizontal 9-max of 4 outputs from 12 smem floats at row r, col c0
__device__ __forceinline__ float4 hmax_row(const float* sm, int r, int c0) {
    const float* rp = sm + r * PITCH + c0;
    const float4 a = *(const float4*)rp;
    const float4 b = *(const float4*)(rp + 4);
    const float4 c = *(const float4*)(rp + 8);
    const float q  = fmaxf(fmaxf(b.x, b.y), fmaxf(b.z, b.w));  // v4..v7
    const float s3 = a.w;
    const float s2 = fmaxf(a.z, s3);
    const float s1 = fmaxf(a.y, s2);
    const float s0 = fmaxf(a.x, s1);
    const float p8 = c.x;
    const float p9  = fmaxf(p8, c.y);
    const float p10 = fmaxf(p9, c.z);
    const float p11 = fmaxf(p10, c.w);
    float4 o;
    o.x = fmaxf(fmaxf(s0, q), p8);
    o.y = fmaxf(fmaxf(s1, q), p9);
    o.z = fmaxf(fmaxf(s2, q), p10);
    o.w = fmaxf(fmaxf(s3, q), p11);
    return o;
}

__global__ __launch_bounds__(NTH)
void dilate9_kernel(const float* __restrict__ in, float* __restrict__ out) {
    extern __shared__ __align__(16) float sm[];   // RAW_H x PITCH
    __shared__ __align__(8) unsigned long long mbar[2];

    const int bx = blockIdx.x;        // x tile (0..3)
    const int by = blockIdx.y;        // y tile (0..15)
    const int bz = blockIdx.z;        // batch
    const int tid = threadIdx.x;

    const float* img = in  + (size_t)bz * IMG * IMG;
    float*      oimg = out + (size_t)bz * IMG * IMG;

    const int x0 = bx * TILE_W;
    const int y0 = by * TILE_H;

    const uint32_t sbase = (uint32_t)__cvta_generic_to_shared(sm);
    const uint32_t mb0 = (uint32_t)__cvta_generic_to_shared(&mbar[0]);
    const uint32_t mb1 = (uint32_t)__cvta_generic_to_shared(&mbar[1]);

    if (tid == 0) {
        mbar_init(mb0, NTH);
        mbar_init(mb1, NTH);
    }
    __syncthreads();   // mbarrier init visible before any arrive

    // ---- group 0: raw rows 0..39 ----
    #pragma unroll 4
    for (int i = tid; i < G0_ROWS * QPR; i += NTH) {
        const int row = i / QPR;
        const int q   = i - row * QPR;
        const int gy = y0 - 4 + row;
        const int gx = x0 - 4 + q * 4;
        const bool v = ((unsigned)gy < (unsigned)IMG) &&
                       ((unsigned)gx <= (unsigned)(IMG - 4));
        const float* src = img + (v ? ((size_t)gy * IMG + gx) : 0);
        cp16(sbase + (uint32_t)(row * QPR + q) * 16u, src, v);
    }
    cp_arrive_noinc(mb0);

    // ---- group 1: raw rows 40..71 ----
    #pragma unroll 4
    for (int i = tid; i < (RAW_H - G0_ROWS) * QPR; i += NTH) {
        const int row = G0_ROWS + i / QPR;
        const int q   = i % QPR;
        const int gy = y0 - 4 + row;
        const int gx = x0 - 4 + q * 4;
        const bool v = ((unsigned)gy < (unsigned)IMG) &&
                       ((unsigned)gx <= (unsigned)(IMG - 4));
        const float* src = img + (v ? ((size_t)gy * IMG + gx) : 0);
        cp16(sbase + (uint32_t)(row * QPR + q) * 16u, src, v);
    }
    cp_arrive_noinc(mb1);

    // ---- compute: 64 col groups x 4 row streams of 16 out rows ----
    const int g  = tid & 63;          // col group: 4 cols (16B stride, no conflicts)
    const int rs = tid >> 6;          // row stream 0..3
    const int c0 = g * 4;             // smem col of first window element
    const int r0 = rs * 16;           // first raw row of stream

    // rs 0..1 need raw rows 0..39 (group 0); rs 2..3 need rows 32..71 (all)
    if (rs < 2) mbar_wait(mb0);
    else        mbar_wait(mb1);

    // chunk 1: suffix over hm rows r0..r0+7
    float4 S[8];
    #pragma unroll
    for (int j = 0; j < 8; j++) S[j] = hmax_row(sm, r0 + j, c0);
    #pragma unroll
    for (int j = 6; j >= 0; j--) S[j] = max4(S[j], S[j + 1]);

    // chunk 1 stream: hm rows r0+8..r0+15 (saved in H), emit out rows 0..7
    float4 H[8];
    float4 P;
    const int oy0 = y0 + rs * 16;
    #pragma unroll
    for (int t = 0; t < 8; t++) {
        H[t] = hmax_row(sm, r0 + 8 + t, c0);
        P = (t == 0) ? H[t] : max4(P, H[t]);
        const float4 o = max4(S[t], P);
        *(float4*)(oimg + (size_t)(oy0 + t) * IMG + x0 + c0) = o;
    }

    // chunk 2: suffix of H in place (H[t] = max of original H[t..7])
    #pragma unroll
    for (int j = 6; j >= 0; j--) H[j] = max4(H[j], H[j + 1]);

    // chunk 2 stream: hm rows r0+16..r0+23, emit out rows 8..15
    #pragma unroll
    for (int t = 0; t < 8; t++) {
        const float4 hm = hmax_row(sm, r0 + 16 + t, c0);
        P = (t == 0) ? hm : max4(P, hm);
        const float4 o = max4(H[t], P);
        *(float4*)(oimg + (size_t)(oy0 + 8 + t) * IMG + x0 + c0) = o;
    }
}

extern "C" void kernel_launch(void* const* d_in, const int* in_sizes, int n_in,
                              void* d_out, int out_size) {
    const float* in = (const float*)d_in[0];
    float* out = (float*)d_out;
    const int batch = in_sizes[0] / (IMG * IMG);

    cudaFuncSetAttribute(dilate9_kernel,
                         cudaFuncAttributeMaxDynamicSharedMemorySize, SMEM_BYTES);

    dim3 grid(IMG / TILE_W, IMG / TILE_H, batch);
    dilate9_kernel<<<grid, NTH, SMEM_BYTES>>>(in, out);
}